// round 4
// baseline (speedup 1.0000x reference)
#include <cuda_runtime.h>
#include <cstdint>
#include <cstddef>

#define BS   256
#define HID  1024
#define NT   100
#define ACT  32
#define KIN  8000
#define G3   3072
#define OUTD 64

// Scratch (allocation-free rule: __device__ globals)
__device__ float g_h0[BS * HID];
__device__ float g_outs[(size_t)NT * BS * HID];     // [t][b][hid]
__device__ float g_gi[(size_t)NT * BS * G3];        // [t][b][3*HID] = a@Wi + bi
__device__ unsigned g_bar;                          // persistent-kernel barrier

// Packed fp32x2 FMA — sm_103a FFMA2; PTX-only (ptxas won't auto-fuse).
__device__ __forceinline__ float2 ffma2(float2 a, float2 b, float2 c) {
    union U { float2 f; unsigned long long u; };
    U A, B, C, D;
    A.f = a; B.f = b; C.f = c;
    asm("fma.rn.f32x2 %0, %1, %2, %3;" : "=l"(D.u) : "l"(A.u), "l"(B.u), "l"(C.u));
    return D.f;
}

__device__ __forceinline__ float fast_sigmoid(float x) {
    return __fdividef(1.0f, 1.0f + __expf(-x));
}
__device__ __forceinline__ float fast_tanh(float x) {
    float e = __expf(2.0f * x);
    return 1.0f - __fdividef(2.0f, e + 1.0f);
}

#define CP4(dst, src)  asm volatile("cp.async.ca.shared.global [%0], [%1], 4;\n"  :: "r"(dst), "l"(src))
#define CP16(dst, src) asm volatile("cp.async.cg.shared.global [%0], [%1], 16;\n" :: "r"(dst), "l"(src))
#define CP_COMMIT()    asm volatile("cp.async.commit_group;\n")
#define CP_WAIT(n)     asm volatile("cp.async.wait_group %0;\n" :: "n"(n))

// ===========================================================================
// k_zero: reset the persistent barrier counter (runs each replay)
// ===========================================================================
__global__ void k_zero() { g_bar = 0u; }

// ===========================================================================
// k_gi: GI[t*BS+b][3072] = action[b,t,:] @ Wi + bi    (t-parallel, one shot)
// grid (48, 8, 100), block (16,16)
// ===========================================================================
__global__ void __launch_bounds__(256) k_gi(const float* __restrict__ action,
                                            const float* __restrict__ Wi,
                                            const float* __restrict__ bi,
                                            float* __restrict__ gi) {
    __shared__ float As[32][33];
    __shared__ float Bs[32][64];
    const int tx = threadIdx.x, ty = threadIdx.y;
    const int tid = ty * 16 + tx;
    const int t = blockIdx.z;
    const int b0 = blockIdx.y * 32, n0 = blockIdx.x * 64;

    #pragma unroll
    for (int i = tid; i < 32 * 32; i += 256) {
        int m = i >> 5, k = i & 31;
        As[k][m] = action[(size_t)(b0 + m) * (NT * ACT) + t * ACT + k];
    }
    #pragma unroll
    for (int i = tid; i < 32 * 64; i += 256) {
        int k = i >> 6, n = i & 63;
        Bs[k][n] = Wi[(size_t)k * G3 + n0 + n];
    }
    __syncthreads();

    float2 acc[2][2] = {};
    #pragma unroll
    for (int k = 0; k < 32; k++) {
        float a0 = As[k][ty * 2 + 0], a1 = As[k][ty * 2 + 1];
        float2 A0 = make_float2(a0, a0), A1 = make_float2(a1, a1);
        const float2* bp = reinterpret_cast<const float2*>(&Bs[k][tx * 4]);
        float2 b0v = bp[0], b1v = bp[1];
        acc[0][0] = ffma2(A0, b0v, acc[0][0]);
        acc[0][1] = ffma2(A0, b1v, acc[0][1]);
        acc[1][0] = ffma2(A1, b0v, acc[1][0]);
        acc[1][1] = ffma2(A1, b1v, acc[1][1]);
    }
    #pragma unroll
    for (int r = 0; r < 2; r++) {
        size_t row = (size_t)t * BS + b0 + ty * 2 + r;
        #pragma unroll
        for (int c = 0; c < 2; c++) {
            int n = n0 + tx * 4 + c * 2;
            gi[row * G3 + n]     = acc[r][c].x + bi[n];
            gi[row * G3 + n + 1] = acc[r][c].y + bi[n + 1];
        }
    }
}

// ===========================================================================
// k_h0v2: h0 = relu(X @ W_in + b_in), 512 thr = 4 K-groups, 3-stage cp.async
// grid (16, 8)
// ===========================================================================
#define HBK   16
#define HKPER 2000
#define HNT   125
#define HASZ  (HBK * 36)        // 576
#define HBSZ  (HBK * 64)        // 1024
#define HSTG  (HASZ + HBSZ)     // 1600
#define HGRP  (3 * HSTG)        // 4800
#define HSMF  (4 * HGRP)        // 19200 floats = 76800 B

__global__ void __launch_bounds__(512) k_h0v2(const float* __restrict__ X,
                                              const float* __restrict__ W,
                                              const float* __restrict__ bias,
                                              float* __restrict__ H0) {
    extern __shared__ float sm[];
    const int tid  = threadIdx.x;
    const int g    = tid >> 7;
    const int wtid = tid & 127;
    const int tx   = wtid & 15;
    const int ty   = wtid >> 4;
    const int m0 = blockIdx.y * 32, n0 = blockIdx.x * 64;
    float* gb = sm + g * HGRP;

    float b4x = bias[n0 + (tid & 15) * 4 + 0];
    float b4y = bias[n0 + (tid & 15) * 4 + 1];
    float b4z = bias[n0 + (tid & 15) * 4 + 2];
    float b4w = bias[n0 + (tid & 15) * 4 + 3];

    float2 acc[4][2] = {};

    auto load_tile = [&](int stage, int tl) {
        const int kb = g * HKPER + tl * HBK;
        float* dstA = gb + stage * HSTG;
        const float* asrc = X + (size_t)m0 * KIN + kb;
        #pragma unroll
        for (int i = wtid; i < HBK * 32; i += 128) {
            int k = i & 15, m = i >> 4;
            uint32_t d = (uint32_t)__cvta_generic_to_shared(dstA + k * 36 + m);
            CP4(d, asrc + (size_t)m * KIN + k);
        }
        const float* bsrc = W + (size_t)kb * HID + n0;
        float* dstB = dstA + HASZ;
        #pragma unroll
        for (int i = wtid; i < HBK * 16; i += 128) {
            int k = i >> 4, n4 = i & 15;
            uint32_t d = (uint32_t)__cvta_generic_to_shared(dstB + k * 64 + n4 * 4);
            CP16(d, bsrc + (size_t)k * HID + n4 * 4);
        }
    };

    auto compute = [&](int stage) {
        const float* As_ = gb + stage * HSTG;
        const float* B_  = As_ + HASZ;
        #pragma unroll
        for (int k = 0; k < HBK; k++) {
            float4 a4 = *reinterpret_cast<const float4*>(As_ + k * 36 + ty * 4);
            float2 A0 = make_float2(a4.x, a4.x), A1 = make_float2(a4.y, a4.y);
            float2 A2 = make_float2(a4.z, a4.z), A3 = make_float2(a4.w, a4.w);
            float4 b = *reinterpret_cast<const float4*>(B_ + k * 64 + tx * 4);
            float2 b0 = make_float2(b.x, b.y), b1 = make_float2(b.z, b.w);
            acc[0][0] = ffma2(A0, b0, acc[0][0]); acc[0][1] = ffma2(A0, b1, acc[0][1]);
            acc[1][0] = ffma2(A1, b0, acc[1][0]); acc[1][1] = ffma2(A1, b1, acc[1][1]);
            acc[2][0] = ffma2(A2, b0, acc[2][0]); acc[2][1] = ffma2(A2, b1, acc[2][1]);
            acc[3][0] = ffma2(A3, b0, acc[3][0]); acc[3][1] = ffma2(A3, b1, acc[3][1]);
        }
    };

    load_tile(0, 0); CP_COMMIT();
    load_tile(1, 1); CP_COMMIT();
    int cs = 0, ls = 2;
    for (int tl = 0; tl < HNT; tl++) {
        CP_WAIT(1);
        __syncthreads();
        if (tl + 2 < HNT) load_tile(ls, tl + 2);
        CP_COMMIT();
        compute(cs);
        cs = (cs == 2) ? 0 : cs + 1;
        ls = (ls == 2) ? 0 : ls + 1;
    }

    // RACE FIX: all threads must finish compute before stage smem is reused.
    __syncthreads();

    // partials to own smem region, then parallel reduce+relu
    #pragma unroll
    for (int r = 0; r < 4; r++) {
        float4 v = make_float4(acc[r][0].x, acc[r][0].y, acc[r][1].x, acc[r][1].y);
        *reinterpret_cast<float4*>(gb + (ty * 4 + r) * 64 + tx * 4) = v;
    }
    __syncthreads();

    {
        int row = tid >> 4, c0 = (tid & 15) * 4;
        float s0 = 0.f, s1 = 0.f, s2 = 0.f, s3 = 0.f;
        #pragma unroll
        for (int gg = 0; gg < 4; gg++) {
            float4 p = *reinterpret_cast<const float4*>(sm + gg * HGRP + row * 64 + c0);
            s0 += p.x; s1 += p.y; s2 += p.z; s3 += p.w;
        }
        s0 += b4x; s1 += b4y; s2 += b4z; s3 += b4w;
        float4 o = make_float4(s0 > 0.f ? s0 : 0.f, s1 > 0.f ? s1 : 0.f,
                               s2 > 0.f ? s2 : 0.f, s3 > 0.f ? s3 : 0.f);
        *reinterpret_cast<float4*>(H0 + (size_t)(m0 + row) * HID + n0 + c0) = o;
    }
}

// ===========================================================================
// k_steps: PERSISTENT GRU recurrence. One launch; internal loop over t with
// a global spin barrier between steps. 128 blocks (1/SM, all resident).
// 512 thr = 4 K-groups x 128; 3-stage cp.async; parallel epilogue.
// ===========================================================================
#define BK3    16
#define NTIL3  16               // KPER 256 / 16
#define KPER3  256
#define ASZ3   (BK3 * 36)       // 576
#define BSZ3   (3 * BK3 * 64)   // 3072
#define STG3   (ASZ3 + BSZ3)    // 3648
#define GRP3   (3 * STG3)       // 10944
#define GIOFF  (4 * GRP3)       // 43776
#define HPOFF  (GIOFF + 3 * 2048)
#define SMF3   (HPOFF + 2048)   // 51968 floats = 207872 B
#define NBLK   128

__global__ void __launch_bounds__(512) k_steps(const float* __restrict__ h0,
                                               const float* __restrict__ gi,
                                               const float* __restrict__ Wh,
                                               const float* __restrict__ bhn,
                                               float* __restrict__ outs) {
    extern __shared__ float sm[];
    const int tid  = threadIdx.x;
    const int g    = tid >> 7;
    const int wtid = tid & 127;
    const int tx   = wtid & 15;
    const int ty   = wtid >> 4;
    const int m0 = blockIdx.y * 32, n0 = blockIdx.x * 64;
    float* gb = sm + g * GRP3;

    const int ec0 = (tid & 15) * 4;
    const int erow = tid >> 4;
    const float bh0 = bhn[n0 + ec0 + 0], bh1 = bhn[n0 + ec0 + 1];
    const float bh2 = bhn[n0 + ec0 + 2], bh3 = bhn[n0 + ec0 + 3];

    const float* hprev = h0;

    #pragma unroll 1
    for (int t = 0; t < NT; t++) {
        const float* gi_t = gi + (size_t)t * BS * G3;
        float* hout = outs + (size_t)t * BS * HID;

        // prefetch GI tile (3 gates x 32 x 64) and hprev blend tile (32 x 64)
        {
            uint32_t d = (uint32_t)__cvta_generic_to_shared(sm + HPOFF + erow * 64 + ec0);
            CP16(d, hprev + (size_t)(m0 + erow) * HID + n0 + ec0);
            #pragma unroll
            for (int gate = 0; gate < 3; gate++) {
                uint32_t dg = (uint32_t)__cvta_generic_to_shared(sm + GIOFF + gate * 2048 + erow * 64 + ec0);
                CP16(dg, gi_t + (size_t)(m0 + erow) * G3 + gate * HID + n0 + ec0);
            }
        }
        CP_COMMIT();

        float2 acc[3][4][2] = {};

        auto load_tile = [&](int stage, int tl) {
            const int kb = g * KPER3 + tl * BK3;
            float* dstA = gb + stage * STG3;
            const float* asrc = hprev + (size_t)m0 * HID + kb;
            #pragma unroll
            for (int i = wtid; i < BK3 * 32; i += 128) {
                int k = i & 15, m = i >> 4;
                uint32_t d = (uint32_t)__cvta_generic_to_shared(dstA + k * 36 + m);
                CP4(d, asrc + (size_t)m * HID + k);
            }
            const float* bsrc = Wh + (size_t)kb * G3 + n0;
            float* dstB = dstA + ASZ3;
            #pragma unroll
            for (int i = wtid; i < 3 * BK3 * 16; i += 128) {
                int gate = i >> 8, rem = i & 255, k = rem >> 4, n4 = rem & 15;
                uint32_t d = (uint32_t)__cvta_generic_to_shared(dstB + gate * (BK3 * 64) + k * 64 + n4 * 4);
                CP16(d, bsrc + (size_t)k * G3 + gate * HID + n4 * 4);
            }
        };

        auto compute = [&](int stage) {
            const float* As_ = gb + stage * STG3;
            const float* B_  = As_ + ASZ3;
            #pragma unroll
            for (int k = 0; k < BK3; k++) {
                float4 a4 = *reinterpret_cast<const float4*>(As_ + k * 36 + ty * 4);
                float2 A0 = make_float2(a4.x, a4.x), A1 = make_float2(a4.y, a4.y);
                float2 A2 = make_float2(a4.z, a4.z), A3 = make_float2(a4.w, a4.w);
                #pragma unroll
                for (int gate = 0; gate < 3; gate++) {
                    float4 b = *reinterpret_cast<const float4*>(B_ + gate * (BK3 * 64) + k * 64 + tx * 4);
                    float2 b0 = make_float2(b.x, b.y), b1 = make_float2(b.z, b.w);
                    acc[gate][0][0] = ffma2(A0, b0, acc[gate][0][0]);
                    acc[gate][0][1] = ffma2(A0, b1, acc[gate][0][1]);
                    acc[gate][1][0] = ffma2(A1, b0, acc[gate][1][0]);
                    acc[gate][1][1] = ffma2(A1, b1, acc[gate][1][1]);
                    acc[gate][2][0] = ffma2(A2, b0, acc[gate][2][0]);
                    acc[gate][2][1] = ffma2(A2, b1, acc[gate][2][1]);
                    acc[gate][3][0] = ffma2(A3, b0, acc[gate][3][0]);
                    acc[gate][3][1] = ffma2(A3, b1, acc[gate][3][1]);
                }
            }
        };

        load_tile(0, 0); CP_COMMIT();
        load_tile(1, 1); CP_COMMIT();
        int cs = 0, ls = 2;
        #pragma unroll 1
        for (int tl = 0; tl < NTIL3; tl++) {
            CP_WAIT(1);
            __syncthreads();
            if (tl + 2 < NTIL3) load_tile(ls, tl + 2);
            CP_COMMIT();
            compute(cs);
            cs = (cs == 2) ? 0 : cs + 1;
            ls = (ls == 2) ? 0 : ls + 1;
        }

        // RACE FIX: all threads must finish compute before stage smem is reused.
        __syncthreads();

        // each group dumps partials into its own (dead) stage region
        #pragma unroll
        for (int gate = 0; gate < 3; gate++)
            #pragma unroll
            for (int r = 0; r < 4; r++) {
                float4 v = make_float4(acc[gate][r][0].x, acc[gate][r][0].y,
                                       acc[gate][r][1].x, acc[gate][r][1].y);
                *reinterpret_cast<float4*>(gb + gate * 2048 + (ty * 4 + r) * 64 + tx * 4) = v;
            }
        __syncthreads();

        // parallel epilogue: reduce 4 partials, gates, blend, store 4 outputs
        {
            float rr0 = 0.f, rr1 = 0.f, rr2 = 0.f, rr3 = 0.f;
            float zz0 = 0.f, zz1 = 0.f, zz2 = 0.f, zz3 = 0.f;
            float hh0 = 0.f, hh1 = 0.f, hh2 = 0.f, hh3 = 0.f;
            #pragma unroll
            for (int gg = 0; gg < 4; gg++) {
                const float* red = sm + gg * GRP3;
                float4 pr = *reinterpret_cast<const float4*>(red + 0 * 2048 + erow * 64 + ec0);
                float4 pz = *reinterpret_cast<const float4*>(red + 1 * 2048 + erow * 64 + ec0);
                float4 pn = *reinterpret_cast<const float4*>(red + 2 * 2048 + erow * 64 + ec0);
                rr0 += pr.x; rr1 += pr.y; rr2 += pr.z; rr3 += pr.w;
                zz0 += pz.x; zz1 += pz.y; zz2 += pz.z; zz3 += pz.w;
                hh0 += pn.x; hh1 += pn.y; hh2 += pn.z; hh3 += pn.w;
            }
            float4 gr = *reinterpret_cast<const float4*>(sm + GIOFF + 0 * 2048 + erow * 64 + ec0);
            float4 gz = *reinterpret_cast<const float4*>(sm + GIOFF + 1 * 2048 + erow * 64 + ec0);
            float4 gn = *reinterpret_cast<const float4*>(sm + GIOFF + 2 * 2048 + erow * 64 + ec0);
            float4 hp = *reinterpret_cast<const float4*>(sm + HPOFF + erow * 64 + ec0);

            float4 o;
            {
                float rg = fast_sigmoid(rr0 + gr.x);
                float zg = fast_sigmoid(zz0 + gz.x);
                float ng = fast_tanh(gn.x + rg * (hh0 + bh0));
                o.x = (1.0f - zg) * ng + zg * hp.x;
            }
            {
                float rg = fast_sigmoid(rr1 + gr.y);
                float zg = fast_sigmoid(zz1 + gz.y);
                float ng = fast_tanh(gn.y + rg * (hh1 + bh1));
                o.y = (1.0f - zg) * ng + zg * hp.y;
            }
            {
                float rg = fast_sigmoid(rr2 + gr.z);
                float zg = fast_sigmoid(zz2 + gz.z);
                float ng = fast_tanh(gn.z + rg * (hh2 + bh2));
                o.z = (1.0f - zg) * ng + zg * hp.z;
            }
            {
                float rg = fast_sigmoid(rr3 + gr.w);
                float zg = fast_sigmoid(zz3 + gz.w);
                float ng = fast_tanh(gn.w + rg * (hh3 + bh3));
                o.w = (1.0f - zg) * ng + zg * hp.w;
            }
            *reinterpret_cast<float4*>(hout + (size_t)(m0 + erow) * HID + n0 + ec0) = o;
        }

        // ---- global barrier between steps (skip after last step) ----
        if (t + 1 < NT) {
            __threadfence();                 // each thread publishes its STG
            __syncthreads();                 // all threads of block fenced
            if (tid == 0) {
                const unsigned target = (unsigned)NBLK * (unsigned)(t + 1);
                atomicAdd(&g_bar, 1u);
                unsigned v;
                do {
                    asm volatile("ld.volatile.global.u32 %0, [%1];"
                                 : "=r"(v) : "l"(&g_bar));
                } while (v < target);
            }
            __syncthreads();
            __threadfence();                 // acquire side
        }
        hprev = hout;
    }
}

// ===========================================================================
// k_out: out[b][t][:] = outs[t][b][:] @ Wo + bo
// ===========================================================================
__global__ void __launch_bounds__(256) k_out(const float* __restrict__ outs,
                                             const float* __restrict__ Wo,
                                             const float* __restrict__ bo,
                                             float* __restrict__ out) {
    __shared__ float As[32][33];
    __shared__ float Bs[32][64];
    const int tx = threadIdx.x, ty = threadIdx.y;
    const int tid = ty * 16 + tx;
    const int R0 = blockIdx.x * 32;
    float2 acc[2][2] = {};

    for (int k0 = 0; k0 < HID; k0 += 32) {
        #pragma unroll
        for (int i = tid; i < 32 * 32; i += 256) {
            int m = i >> 5, k = i & 31;
            As[k][m] = outs[(size_t)(R0 + m) * HID + k0 + k];
        }
        #pragma unroll
        for (int i = tid; i < 32 * 64; i += 256) {
            int k = i >> 6, n = i & 63;
            Bs[k][n] = Wo[(size_t)(k0 + k) * OUTD + n];
        }
        __syncthreads();
        #pragma unroll
        for (int k = 0; k < 32; k++) {
            float a0 = As[k][ty * 2 + 0], a1 = As[k][ty * 2 + 1];
            float2 A0 = make_float2(a0, a0), A1 = make_float2(a1, a1);
            const float2* bp = reinterpret_cast<const float2*>(&Bs[k][tx * 4]);
            float2 b0 = bp[0], b1 = bp[1];
            acc[0][0] = ffma2(A0, b0, acc[0][0]);
            acc[0][1] = ffma2(A0, b1, acc[0][1]);
            acc[1][0] = ffma2(A1, b0, acc[1][0]);
            acc[1][1] = ffma2(A1, b1, acc[1][1]);
        }
        __syncthreads();
    }

    #pragma unroll
    for (int r = 0; r < 2; r++) {
        int R = R0 + ty * 2 + r;       // R = t*BS + b
        int tt = R >> 8;
        int b  = R & (BS - 1);
        #pragma unroll
        for (int c = 0; c < 2; c++) {
            int n = tx * 4 + c * 2;
            out[((size_t)b * NT + tt) * OUTD + n]     = acc[r][c].x + bo[n];
            out[((size_t)b * NT + tt) * OUTD + n + 1] = acc[r][c].y + bo[n + 1];
        }
    }
}

extern "C" void kernel_launch(void* const* d_in, const int* in_sizes, int n_in,
                              void* d_out, int out_size) {
    const float* history = (const float*)d_in[0];
    const float* action  = (const float*)d_in[1];
    const float* W_in    = (const float*)d_in[2];
    const float* b_in    = (const float*)d_in[3];
    const float* Wi      = (const float*)d_in[4];
    const float* bi      = (const float*)d_in[5];
    const float* Wh      = (const float*)d_in[6];
    const float* bhn     = (const float*)d_in[7];
    const float* Wo      = (const float*)d_in[8];
    const float* bo      = (const float*)d_in[9];
    float* out = (float*)d_out;

    float *h0buf = nullptr, *outsbuf = nullptr, *gibuf = nullptr;
    cudaGetSymbolAddress((void**)&h0buf, g_h0);
    cudaGetSymbolAddress((void**)&outsbuf, g_outs);
    cudaGetSymbolAddress((void**)&gibuf, g_gi);

    const int smem_step = SMF3 * 4;   // 207,872 B
    const int smem_h0   = HSMF * 4;   // 76,800 B
    cudaFuncSetAttribute(k_steps, cudaFuncAttributeMaxDynamicSharedMemorySize, smem_step);
    cudaFuncSetAttribute(k_h0v2, cudaFuncAttributeMaxDynamicSharedMemorySize, smem_h0);

    k_zero<<<1, 1>>>();
    k_h0v2<<<dim3(HID / 64, BS / 32), 512, smem_h0>>>(history, W_in, b_in, h0buf);
    k_gi<<<dim3(G3 / 64, BS / 32, NT), dim3(16, 16)>>>(action, Wi, bi, gibuf);

    k_steps<<<dim3(HID / 64, BS / 32), 512, smem_step>>>(h0buf, gibuf, Wh, bhn, outsbuf);

    k_out<<<dim3(NT * BS / 32), dim3(16, 16)>>>(outsbuf, Wo, bo, out);
}

// round 6
// speedup vs baseline: 1.5578x; 1.5578x over previous
#include <cuda_runtime.h>
#include <cuda_bf16.h>
#include <cstdint>
#include <cstddef>

#define BS   256
#define HID  1024
#define NT   100
#define ACT  32
#define KIN  8000
#define G3   3072
#define OUTD 64
#define NBLK 128

// ---------------- device scratch (allocation-free rule) ----------------
__device__ float g_h0[BS * HID];
__device__ float g_outs[(size_t)NT * BS * HID];     // [t][b][hid]
__device__ float g_gi[(size_t)NT * BS * G3];        // [t][b][3*HID] = a@Wi + bi
__device__ unsigned g_bar;                          // persistent barrier

// h (A) bf16 images, double buffered across steps: [buf 2][m 256][k 1024]
__device__ __align__(16) unsigned short g_hA_hi[2 * BS * HID];   // 1 MB
__device__ __align__(16) unsigned short g_hA_lo[2 * BS * HID];
// Wh (B) packed bf16: [slice 32][k 1024][col 96]
// col c = sub*48 + gate*16 + h16;  hid = s*32 + sub*16 + h16
__device__ __align__(16) unsigned short g_wBp_hi[32 * HID * 96]; // 6.3 MB
__device__ __align__(16) unsigned short g_wBp_lo[32 * HID * 96];

// ---------------- helpers ----------------
__device__ __forceinline__ float2 ffma2(float2 a, float2 b, float2 c) {
    union U { float2 f; unsigned long long u; };
    U A, B, C, D;
    A.f = a; B.f = b; C.f = c;
    asm("fma.rn.f32x2 %0, %1, %2, %3;" : "=l"(D.u) : "l"(A.u), "l"(B.u), "l"(C.u));
    return D.f;
}
__device__ __forceinline__ float fast_sigmoid(float x) {
    return __fdividef(1.0f, 1.0f + __expf(-x));
}
__device__ __forceinline__ float fast_tanh(float x) {
    float e = __expf(2.0f * x);
    return 1.0f - __fdividef(2.0f, e + 1.0f);
}
__device__ __forceinline__ void split2(float x, unsigned short& h, unsigned short& l) {
    __nv_bfloat16 hb = __float2bfloat16(x);
    float hf = __bfloat162float(hb);
    __nv_bfloat16 lb = __float2bfloat16(x - hf);
    h = *reinterpret_cast<unsigned short*>(&hb);
    l = *reinterpret_cast<unsigned short*>(&lb);
}

#define CP4(dst, src)  asm volatile("cp.async.ca.shared.global [%0], [%1], 4;\n"  :: "r"(dst), "l"(src))
#define CP16(dst, src) asm volatile("cp.async.cg.shared.global [%0], [%1], 16;\n" :: "r"(dst), "l"(src))
#define CP_COMMIT()    asm volatile("cp.async.commit_group;\n")
#define CP_WAIT(n)     asm volatile("cp.async.wait_group %0;\n" :: "n"(n))

__device__ __forceinline__ uint32_t smem_u32(const void* p) {
    uint32_t a;
    asm("{ .reg .u64 t; cvta.to.shared.u64 t, %1; cvt.u32.u64 %0, t; }" : "=r"(a) : "l"(p));
    return a;
}

// mma.sync bf16 (baseline PTX, works on .target sm_103)
__device__ __forceinline__ void mma16816(float* c, const uint32_t* a, const uint32_t* b) {
    asm volatile("mma.sync.aligned.m16n8k16.row.col.f32.bf16.bf16.f32 "
        "{%0,%1,%2,%3}, {%4,%5,%6,%7}, {%8,%9}, {%0,%1,%2,%3};"
        : "+f"(c[0]), "+f"(c[1]), "+f"(c[2]), "+f"(c[3])
        : "r"(a[0]), "r"(a[1]), "r"(a[2]), "r"(a[3]), "r"(b[0]), "r"(b[1]));
}
#define LDSM4(r, addr)                                                          \
    asm volatile("ldmatrix.sync.aligned.m8n8.x4.shared.b16 {%0,%1,%2,%3}, [%4];"\
        : "=r"((r)[0]), "=r"((r)[1]), "=r"((r)[2]), "=r"((r)[3]) : "r"(addr))
#define LDSM4T(r, addr)                                                         \
    asm volatile("ldmatrix.sync.aligned.m8n8.x4.trans.shared.b16 {%0,%1,%2,%3}, [%4];" \
        : "=r"((r)[0]), "=r"((r)[1]), "=r"((r)[2]), "=r"((r)[3]) : "r"(addr))

// ===========================================================================
// k_zero
// ===========================================================================
__global__ void k_zero() { g_bar = 0u; }

// ===========================================================================
// k_packW: Wh[k][3072] -> packed [32][1024][96] bf16 hi/lo. grid (32,16), 256.
// ===========================================================================
__global__ void __launch_bounds__(256) k_packW(const float* __restrict__ Wh) {
    const int s = blockIdx.x, kg = blockIdx.y;
    for (int i = threadIdx.x; i < 64 * 96; i += 256) {
        int k = kg * 64 + i / 96;
        int c = i % 96;
        int sub = c / 48, rem = c % 48;
        int gate = rem / 16, h16 = rem % 16;
        float x = Wh[(size_t)k * G3 + gate * HID + s * 32 + sub * 16 + h16];
        size_t dst = ((size_t)s * HID + k) * 96 + c;
        split2(x, g_wBp_hi[dst], g_wBp_lo[dst]);
    }
}

// ===========================================================================
// k_cvtH0: h0 fp32 -> A image buf 0. grid (256), 256 thr.
// ===========================================================================
__global__ void __launch_bounds__(256) k_cvtH0(const float* __restrict__ H0) {
    const int m = blockIdx.x;
    for (int k = threadIdx.x * 4; k < HID; k += 1024) {
        float4 v = *reinterpret_cast<const float4*>(H0 + (size_t)m * HID + k);
        size_t d = (size_t)m * HID + k;
        split2(v.x, g_hA_hi[d],     g_hA_lo[d]);
        split2(v.y, g_hA_hi[d + 1], g_hA_lo[d + 1]);
        split2(v.z, g_hA_hi[d + 2], g_hA_lo[d + 2]);
        split2(v.w, g_hA_hi[d + 3], g_hA_lo[d + 3]);
    }
}

// ===========================================================================
// k_gi (unchanged)
// ===========================================================================
__global__ void __launch_bounds__(256) k_gi(const float* __restrict__ action,
                                            const float* __restrict__ Wi,
                                            const float* __restrict__ bi,
                                            float* __restrict__ gi) {
    __shared__ float As[32][33];
    __shared__ float Bs[32][64];
    const int tx = threadIdx.x, ty = threadIdx.y;
    const int tid = ty * 16 + tx;
    const int t = blockIdx.z;
    const int b0 = blockIdx.y * 32, n0 = blockIdx.x * 64;

    #pragma unroll
    for (int i = tid; i < 32 * 32; i += 256) {
        int m = i >> 5, k = i & 31;
        As[k][m] = action[(size_t)(b0 + m) * (NT * ACT) + t * ACT + k];
    }
    #pragma unroll
    for (int i = tid; i < 32 * 64; i += 256) {
        int k = i >> 6, n = i & 63;
        Bs[k][n] = Wi[(size_t)k * G3 + n0 + n];
    }
    __syncthreads();

    float2 acc[2][2] = {};
    #pragma unroll
    for (int k = 0; k < 32; k++) {
        float a0 = As[k][ty * 2 + 0], a1 = As[k][ty * 2 + 1];
        float2 A0 = make_float2(a0, a0), A1 = make_float2(a1, a1);
        const float2* bp = reinterpret_cast<const float2*>(&Bs[k][tx * 4]);
        float2 b0v = bp[0], b1v = bp[1];
        acc[0][0] = ffma2(A0, b0v, acc[0][0]);
        acc[0][1] = ffma2(A0, b1v, acc[0][1]);
        acc[1][0] = ffma2(A1, b0v, acc[1][0]);
        acc[1][1] = ffma2(A1, b1v, acc[1][1]);
    }
    #pragma unroll
    for (int r = 0; r < 2; r++) {
        size_t row = (size_t)t * BS + b0 + ty * 2 + r;
        #pragma unroll
        for (int c = 0; c < 2; c++) {
            int n = n0 + tx * 4 + c * 2;
            gi[row * G3 + n]     = acc[r][c].x + bi[n];
            gi[row * G3 + n + 1] = acc[r][c].y + bi[n + 1];
        }
    }
}

// ===========================================================================
// k_h0v2 (unchanged, race-fixed)
// ===========================================================================
#define HBK   16
#define HKPER 2000
#define HNT   125
#define HASZ  (HBK * 36)
#define HBSZ  (HBK * 64)
#define HSTG  (HASZ + HBSZ)
#define HGRP  (3 * HSTG)
#define HSMF  (4 * HGRP)

__global__ void __launch_bounds__(512) k_h0v2(const float* __restrict__ X,
                                              const float* __restrict__ W,
                                              const float* __restrict__ bias,
                                              float* __restrict__ H0) {
    extern __shared__ float sm[];
    const int tid  = threadIdx.x;
    const int g    = tid >> 7;
    const int wtid = tid & 127;
    const int tx   = wtid & 15;
    const int ty   = wtid >> 4;
    const int m0 = blockIdx.y * 32, n0 = blockIdx.x * 64;
    float* gb = sm + g * HGRP;

    float b4x = bias[n0 + (tid & 15) * 4 + 0];
    float b4y = bias[n0 + (tid & 15) * 4 + 1];
    float b4z = bias[n0 + (tid & 15) * 4 + 2];
    float b4w = bias[n0 + (tid & 15) * 4 + 3];

    float2 acc[4][2] = {};

    auto load_tile = [&](int stage, int tl) {
        const int kb = g * HKPER + tl * HBK;
        float* dstA = gb + stage * HSTG;
        const float* asrc = X + (size_t)m0 * KIN + kb;
        #pragma unroll
        for (int i = wtid; i < HBK * 32; i += 128) {
            int k = i & 15, m = i >> 4;
            uint32_t d = (uint32_t)__cvta_generic_to_shared(dstA + k * 36 + m);
            CP4(d, asrc + (size_t)m * KIN + k);
        }
        const float* bsrc = W + (size_t)kb * HID + n0;
        float* dstB = dstA + HASZ;
        #pragma unroll
        for (int i = wtid; i < HBK * 16; i += 128) {
            int k = i >> 4, n4 = i & 15;
            uint32_t d = (uint32_t)__cvta_generic_to_shared(dstB + k * 64 + n4 * 4);
            CP16(d, bsrc + (size_t)k * HID + n4 * 4);
        }
    };

    auto compute = [&](int stage) {
        const float* As_ = gb + stage * HSTG;
        const float* B_  = As_ + HASZ;
        #pragma unroll
        for (int k = 0; k < HBK; k++) {
            float4 a4 = *reinterpret_cast<const float4*>(As_ + k * 36 + ty * 4);
            float2 A0 = make_float2(a4.x, a4.x), A1 = make_float2(a4.y, a4.y);
            float2 A2 = make_float2(a4.z, a4.z), A3 = make_float2(a4.w, a4.w);
            float4 b = *reinterpret_cast<const float4*>(B_ + k * 64 + tx * 4);
            float2 b0 = make_float2(b.x, b.y), b1 = make_float2(b.z, b.w);
            acc[0][0] = ffma2(A0, b0, acc[0][0]); acc[0][1] = ffma2(A0, b1, acc[0][1]);
            acc[1][0] = ffma2(A1, b0, acc[1][0]); acc[1][1] = ffma2(A1, b1, acc[1][1]);
            acc[2][0] = ffma2(A2, b0, acc[2][0]); acc[2][1] = ffma2(A2, b1, acc[2][1]);
            acc[3][0] = ffma2(A3, b0, acc[3][0]); acc[3][1] = ffma2(A3, b1, acc[3][1]);
        }
    };

    load_tile(0, 0); CP_COMMIT();
    load_tile(1, 1); CP_COMMIT();
    int cs = 0, ls = 2;
    for (int tl = 0; tl < HNT; tl++) {
        CP_WAIT(1);
        __syncthreads();
        if (tl + 2 < HNT) load_tile(ls, tl + 2);
        CP_COMMIT();
        compute(cs);
        cs = (cs == 2) ? 0 : cs + 1;
        ls = (ls == 2) ? 0 : ls + 1;
    }
    __syncthreads();

    #pragma unroll
    for (int r = 0; r < 4; r++) {
        float4 v = make_float4(acc[r][0].x, acc[r][0].y, acc[r][1].x, acc[r][1].y);
        *reinterpret_cast<float4*>(gb + (ty * 4 + r) * 64 + tx * 4) = v;
    }
    __syncthreads();

    {
        int row = tid >> 4, c0 = (tid & 15) * 4;
        float s0 = 0.f, s1 = 0.f, s2 = 0.f, s3 = 0.f;
        #pragma unroll
        for (int gg = 0; gg < 4; gg++) {
            float4 p = *reinterpret_cast<const float4*>(sm + gg * HGRP + row * 64 + c0);
            s0 += p.x; s1 += p.y; s2 += p.z; s3 += p.w;
        }
        s0 += b4x; s1 += b4y; s2 += b4z; s3 += b4w;
        float4 o = make_float4(s0 > 0.f ? s0 : 0.f, s1 > 0.f ? s1 : 0.f,
                               s2 > 0.f ? s2 : 0.f, s3 > 0.f ? s3 : 0.f);
        *reinterpret_cast<float4*>(H0 + (size_t)(m0 + row) * HID + n0 + c0) = o;
    }
}

// ===========================================================================
// k_steps_mma: persistent HMMA (mma.sync bf16 hi/lo) GRU recurrence.
// grid (32 slices, 4 m-quarters) = 128 CTAs, 256 threads (8 warps).
// CTA tile M=64, N=96 (= 2 subs x 3 gates x 16 hid cols). Warp 16x48.
// ===========================================================================
#define STG_B  23552
#define OFF_AH 0
#define OFF_AL 5120
#define OFF_BH 10240
#define OFF_BL 16896
#define SMEM_MMA (3 * STG_B)    // 70656 B
#define APITCH_B 80             // A row pitch bytes (40 bf16): 5x16B, odd -> conflict-free
#define BPITCH_B 208            // B row pitch bytes (104 bf16): 13x16B, odd

__global__ void __launch_bounds__(256) k_steps_mma(const float* __restrict__ h0,
                                                   const float* __restrict__ gi,
                                                   const float* __restrict__ bhn,
                                                   float* __restrict__ outs) {
    extern __shared__ char smem[];
    const uint32_t sb = smem_u32(smem);
    const int tid = threadIdx.x;
    const int w = tid >> 5, l = tid & 31;
    const int s = blockIdx.x;          // hid slice (32 cols)
    const int mq = blockIdx.y;         // m quarter (64 rows)
    const int wm = w & 3;              // warp m group (16 rows)
    const int wn = w >> 2;             // warp n half (sub 0/1)
    const int lr = l >> 2;             // frag row 0..7
    const int lc2 = (l & 3) * 2;       // frag col pair base

    // ldmatrix lane addressing
    const int a_row  = wm * 16 + (l & 15);
    const int a_koff = (l >> 4) * 8;
    const int b_krow = (l & 15);
    const int b_noff = wn * 48 + (l >> 4) * 8;

    const int hidbase = s * 32 + wn * 16;
    const float2 bh0 = *reinterpret_cast<const float2*>(bhn + hidbase + lc2);
    const float2 bh1 = *reinterpret_cast<const float2*>(bhn + hidbase + 8 + lc2);

    const float* hprev = h0;

    #pragma unroll 1
    for (int t = 0; t < NT; t++) {
        const int rbuf = t & 1;
        const char* srcAH = (const char*)(g_hA_hi + (size_t)rbuf * BS * HID + (size_t)mq * 64 * HID);
        const char* srcAL = (const char*)(g_hA_lo + (size_t)rbuf * BS * HID + (size_t)mq * 64 * HID);
        const char* srcBH = (const char*)(g_wBp_hi + (size_t)s * HID * 96);
        const char* srcBL = (const char*)(g_wBp_lo + (size_t)s * HID * 96);

        float c[6][4] = {};

        auto load_chunk = [&](int ch, int st) {
            uint32_t base = sb + st * STG_B;
            // A: 64 rows x 64B (32 k) x hi/lo; 256 items of 16B each -> 1/thread
            {
                int row = tid >> 2, seg = tid & 3;
                uint32_t d = base + OFF_AH + row * APITCH_B + seg * 16;
                const char* sa = srcAH + (size_t)row * (HID * 2) + ch * 64 + seg * 16;
                CP16(d, sa);
                uint32_t d2 = base + OFF_AL + row * APITCH_B + seg * 16;
                const char* sa2 = srcAL + (size_t)row * (HID * 2) + ch * 64 + seg * 16;
                CP16(d2, sa2);
            }
            // B: 32 rows x 192B x hi/lo; 384 items
            #pragma unroll
            for (int i = tid; i < 384; i += 256) {
                int r = i / 12, sg = i % 12;
                uint32_t d = base + OFF_BH + r * BPITCH_B + sg * 16;
                const char* sbp = srcBH + ((size_t)(ch * 32 + r)) * 192 + sg * 16;
                CP16(d, sbp);
                uint32_t d2 = base + OFF_BL + r * BPITCH_B + sg * 16;
                const char* sbp2 = srcBL + ((size_t)(ch * 32 + r)) * 192 + sg * 16;
                CP16(d2, sbp2);
            }
        };

        auto compute = [&](int st) {
            uint32_t base = sb + st * STG_B;
            #pragma unroll
            for (int kk = 0; kk < 2; kk++) {
                const int k0 = kk * 16;
                uint32_t aH[4], aL[4];
                uint32_t adA = base + OFF_AH + a_row * APITCH_B + (k0 + a_koff) * 2;
                LDSM4(aH, adA);
                LDSM4(aL, adA + (OFF_AL - OFF_AH));
                uint32_t bH[6][2], bL[6][2];
                #pragma unroll
                for (int g2 = 0; g2 < 3; g2++) {
                    uint32_t adB = base + OFF_BH + (k0 + b_krow) * BPITCH_B + (b_noff + g2 * 16) * 2;
                    uint32_t r4[4];
                    LDSM4T(r4, adB);
                    bH[g2 * 2][0] = r4[0]; bH[g2 * 2][1] = r4[1];
                    bH[g2 * 2 + 1][0] = r4[2]; bH[g2 * 2 + 1][1] = r4[3];
                    LDSM4T(r4, adB + (OFF_BL - OFF_BH));
                    bL[g2 * 2][0] = r4[0]; bL[g2 * 2][1] = r4[1];
                    bL[g2 * 2 + 1][0] = r4[2]; bL[g2 * 2 + 1][1] = r4[3];
                }
                #pragma unroll
                for (int g = 0; g < 6; g++) {
                    mma16816(c[g], aH, bH[g]);
                    mma16816(c[g], aH, bL[g]);
                    mma16816(c[g], aL, bH[g]);
                }
            }
        };

        load_chunk(0, 0); CP_COMMIT();
        load_chunk(1, 1); CP_COMMIT();
        #pragma unroll 1
        for (int ch = 0; ch < 32; ch++) {
            CP_WAIT(1);
            __syncthreads();
            if (ch + 2 < 32) load_chunk(ch + 2, (ch + 2) % 3);
            CP_COMMIT();
            compute(ch % 3);
        }

        // ---- epilogue: lane-local GRU pointwise ----
        #pragma unroll
        for (int rr = 0; rr < 2; rr++) {
            const int m = mq * 64 + wm * 16 + lr + rr * 8;
            const float* gir = gi + ((size_t)t * BS + m) * G3;
            const float* hpr = hprev + (size_t)m * HID;
            float* orow = outs + ((size_t)t * BS + m) * HID;
            #pragma unroll
            for (int pp = 0; pp < 2; pp++) {
                const int hid = hidbase + pp * 8 + lc2;
                float2 gr = *reinterpret_cast<const float2*>(gir + hid);
                float2 gz = *reinterpret_cast<const float2*>(gir + HID + hid);
                float2 gn = *reinterpret_cast<const float2*>(gir + 2 * HID + hid);
                float2 hp = *reinterpret_cast<const float2*>(hpr + hid);
                float2 bh = pp ? bh1 : bh0;
                float h[2];
                #pragma unroll
                for (int e = 0; e < 2; e++) {
                    float rv = c[pp][2 * rr + e];
                    float zv = c[2 + pp][2 * rr + e];
                    float nv = c[4 + pp][2 * rr + e];
                    float rg = fast_sigmoid(rv + (e ? gr.y : gr.x));
                    float zg = fast_sigmoid(zv + (e ? gz.y : gz.x));
                    float ng = fast_tanh((e ? gn.y : gn.x) + rg * (nv + (e ? bh.y : bh.x)));
                    h[e] = (1.0f - zg) * ng + zg * (e ? hp.y : hp.x);
                }
                *reinterpret_cast<float2*>(orow + hid) = make_float2(h[0], h[1]);
                if (t + 1 < NT) {
                    const int wbuf = (t + 1) & 1;
                    size_t d = (size_t)wbuf * BS * HID + (size_t)m * HID + hid;
                    unsigned short hi0, hi1, lo0, lo1;
                    split2(h[0], hi0, lo0);
                    split2(h[1], hi1, lo1);
                    *reinterpret_cast<uint32_t*>(g_hA_hi + d) = ((uint32_t)hi1 << 16) | hi0;
                    *reinterpret_cast<uint32_t*>(g_hA_lo + d) = ((uint32_t)lo1 << 16) | lo0;
                }
            }
        }

        // ---- global barrier between steps ----
        if (t + 1 < NT) {
            __threadfence();
            __syncthreads();
            if (tid == 0) {
                const unsigned target = (unsigned)NBLK * (unsigned)(t + 1);
                atomicAdd(&g_bar, 1u);
                unsigned v;
                do {
                    asm volatile("ld.volatile.global.u32 %0, [%1];" : "=r"(v) : "l"(&g_bar));
                } while (v < target);
            }
            __syncthreads();
            __threadfence();
        }
        hprev = outs + (size_t)t * BS * HID;
    }
}

// ===========================================================================
// k_out (unchanged)
// ===========================================================================
__global__ void __launch_bounds__(256) k_out(const float* __restrict__ outs,
                                             const float* __restrict__ Wo,
                                             const float* __restrict__ bo,
                                             float* __restrict__ out) {
    __shared__ float As[32][33];
    __shared__ float Bs[32][64];
    const int tx = threadIdx.x, ty = threadIdx.y;
    const int tid = ty * 16 + tx;
    const int R0 = blockIdx.x * 32;
    float2 acc[2][2] = {};

    for (int k0 = 0; k0 < HID; k0 += 32) {
        #pragma unroll
        for (int i = tid; i < 32 * 32; i += 256) {
            int m = i >> 5, k = i & 31;
            As[k][m] = outs[(size_t)(R0 + m) * HID + k0 + k];
        }
        #pragma unroll
        for (int i = tid; i < 32 * 64; i += 256) {
            int k = i >> 6, n = i & 63;
            Bs[k][n] = Wo[(size_t)(k0 + k) * OUTD + n];
        }
        __syncthreads();
        #pragma unroll
        for (int k = 0; k < 32; k++) {
            float a0 = As[k][ty * 2 + 0], a1 = As[k][ty * 2 + 1];
            float2 A0 = make_float2(a0, a0), A1 = make_float2(a1, a1);
            const float2* bp = reinterpret_cast<const float2*>(&Bs[k][tx * 4]);
            float2 b0 = bp[0], b1 = bp[1];
            acc[0][0] = ffma2(A0, b0, acc[0][0]);
            acc[0][1] = ffma2(A0, b1, acc[0][1]);
            acc[1][0] = ffma2(A1, b0, acc[1][0]);
            acc[1][1] = ffma2(A1, b1, acc[1][1]);
        }
        __syncthreads();
    }

    #pragma unroll
    for (int r = 0; r < 2; r++) {
        int R = R0 + ty * 2 + r;
        int tt = R >> 8;
        int b  = R & (BS - 1);
        #pragma unroll
        for (int c = 0; c < 2; c++) {
            int n = tx * 4 + c * 2;
            out[((size_t)b * NT + tt) * OUTD + n]     = acc[r][c].x + bo[n];
            out[((size_t)b * NT + tt) * OUTD + n + 1] = acc[r][c].y + bo[n + 1];
        }
    }
}

extern "C" void kernel_launch(void* const* d_in, const int* in_sizes, int n_in,
                              void* d_out, int out_size) {
    const float* history = (const float*)d_in[0];
    const float* action  = (const float*)d_in[1];
    const float* W_in    = (const float*)d_in[2];
    const float* b_in    = (const float*)d_in[3];
    const float* Wi      = (const float*)d_in[4];
    const float* bi      = (const float*)d_in[5];
    const float* Wh      = (const float*)d_in[6];
    const float* bhn     = (const float*)d_in[7];
    const float* Wo      = (const float*)d_in[8];
    const float* bo      = (const float*)d_in[9];
    float* out = (float*)d_out;

    float *h0buf = nullptr, *outsbuf = nullptr, *gibuf = nullptr;
    cudaGetSymbolAddress((void**)&h0buf, g_h0);
    cudaGetSymbolAddress((void**)&outsbuf, g_outs);
    cudaGetSymbolAddress((void**)&gibuf, g_gi);

    const int smem_h0 = HSMF * 4;
    cudaFuncSetAttribute(k_h0v2, cudaFuncAttributeMaxDynamicSharedMemorySize, smem_h0);
    cudaFuncSetAttribute(k_steps_mma, cudaFuncAttributeMaxDynamicSharedMemorySize, SMEM_MMA);

    k_zero<<<1, 1>>>();
    k_h0v2<<<dim3(HID / 64, BS / 32), 512, smem_h0>>>(history, W_in, b_in, h0buf);
    k_gi<<<dim3(G3 / 64, BS / 32, NT), dim3(16, 16)>>>(action, Wi, bi, gibuf);
    k_packW<<<dim3(32, 16), 256>>>(Wh);
    k_cvtH0<<<BS, 256>>>(h0buf);

    k_steps_mma<<<dim3(32, 4), 256, SMEM_MMA>>>(h0buf, gibuf, bhn, outsbuf);

    k_out<<<dim3(NT * BS / 32), dim3(16, 16)>>>(outsbuf, Wo, bo, out);
}

// round 7
// speedup vs baseline: 1.6487x; 1.0584x over previous
#include <cuda_runtime.h>
#include <cuda_bf16.h>
#include <cstdint>
#include <cstddef>

#define BS   256
#define HID  1024
#define NT   100
#define ACT  32
#define KIN  8000
#define G3   3072
#define OUTD 64

// ---------------- device scratch (allocation-free rule) ----------------
__device__ float g_h0[BS * HID];
__device__ float g_outs[(size_t)NT * BS * HID];     // [t][b][hid]
__device__ unsigned g_bars[4 * 32];                 // per-mq barrier counters (128B apart)

// h (A) bf16 images, double buffered across steps: [buf 2][m 256][k 1024]
__device__ __align__(16) unsigned short g_hA_hi[2 * BS * HID];   // 1 MB
__device__ __align__(16) unsigned short g_hA_lo[2 * BS * HID];
// Wh (B) packed bf16: [slice 32][k 1024][col 96]
// col c = sub*48 + gate*16 + h16;  hid = s*32 + sub*16 + h16
__device__ __align__(16) unsigned short g_wBp_hi[32 * HID * 96]; // 6.3 MB
__device__ __align__(16) unsigned short g_wBp_lo[32 * HID * 96];

// ---------------- helpers ----------------
__device__ __forceinline__ float2 ffma2(float2 a, float2 b, float2 c) {
    union U { float2 f; unsigned long long u; };
    U A, B, C, D;
    A.f = a; B.f = b; C.f = c;
    asm("fma.rn.f32x2 %0, %1, %2, %3;" : "=l"(D.u) : "l"(A.u), "l"(B.u), "l"(C.u));
    return D.f;
}
__device__ __forceinline__ float fast_sigmoid(float x) {
    return __fdividef(1.0f, 1.0f + __expf(-x));
}
__device__ __forceinline__ float fast_tanh(float x) {
    float e = __expf(2.0f * x);
    return 1.0f - __fdividef(2.0f, e + 1.0f);
}
__device__ __forceinline__ void split2(float x, unsigned short& h, unsigned short& l) {
    __nv_bfloat16 hb = __float2bfloat16(x);
    float hf = __bfloat162float(hb);
    __nv_bfloat16 lb = __float2bfloat16(x - hf);
    h = *reinterpret_cast<unsigned short*>(&hb);
    l = *reinterpret_cast<unsigned short*>(&lb);
}

#define CP4(dst, src)  asm volatile("cp.async.ca.shared.global [%0], [%1], 4;\n"  :: "r"(dst), "l"(src))
#define CP16(dst, src) asm volatile("cp.async.cg.shared.global [%0], [%1], 16;\n" :: "r"(dst), "l"(src))
#define CP_COMMIT()    asm volatile("cp.async.commit_group;\n")
#define CP_WAIT(n)     asm volatile("cp.async.wait_group %0;\n" :: "n"(n))

__device__ __forceinline__ uint32_t smem_u32(const void* p) {
    uint32_t a;
    asm("{ .reg .u64 t; cvta.to.shared.u64 t, %1; cvt.u32.u64 %0, t; }" : "=r"(a) : "l"(p));
    return a;
}

// mma.sync bf16 (baseline PTX, works on .target sm_103)
__device__ __forceinline__ void mma16816(float* c, const uint32_t* a, const uint32_t* b) {
    asm volatile("mma.sync.aligned.m16n8k16.row.col.f32.bf16.bf16.f32 "
        "{%0,%1,%2,%3}, {%4,%5,%6,%7}, {%8,%9}, {%0,%1,%2,%3};"
        : "+f"(c[0]), "+f"(c[1]), "+f"(c[2]), "+f"(c[3])
        : "r"(a[0]), "r"(a[1]), "r"(a[2]), "r"(a[3]), "r"(b[0]), "r"(b[1]));
}
#define LDSM4(r, addr)                                                          \
    asm volatile("ldmatrix.sync.aligned.m8n8.x4.shared.b16 {%0,%1,%2,%3}, [%4];"\
        : "=r"((r)[0]), "=r"((r)[1]), "=r"((r)[2]), "=r"((r)[3]) : "r"(addr))
#define LDSM4T(r, addr)                                                         \
    asm volatile("ldmatrix.sync.aligned.m8n8.x4.trans.shared.b16 {%0,%1,%2,%3}, [%4];" \
        : "=r"((r)[0]), "=r"((r)[1]), "=r"((r)[2]), "=r"((r)[3]) : "r"(addr))

// ===========================================================================
// k_zero
// ===========================================================================
__global__ void k_zero() {
    if (threadIdx.x < 4 * 32) g_bars[threadIdx.x] = 0u;
}

// ===========================================================================
// k_packW: Wh[k][3072] -> packed [32][1024][96] bf16 hi/lo. grid (32,16), 256.
// ===========================================================================
__global__ void __launch_bounds__(256) k_packW(const float* __restrict__ Wh) {
    const int s = blockIdx.x, kg = blockIdx.y;
    for (int i = threadIdx.x; i < 64 * 96; i += 256) {
        int k = kg * 64 + i / 96;
        int c = i % 96;
        int sub = c / 48, rem = c % 48;
        int gate = rem / 16, h16 = rem % 16;
        float x = Wh[(size_t)k * G3 + gate * HID + s * 32 + sub * 16 + h16];
        size_t dst = ((size_t)s * HID + k) * 96 + c;
        split2(x, g_wBp_hi[dst], g_wBp_lo[dst]);
    }
}

// ===========================================================================
// k_cvtH0: h0 fp32 -> A image buf 0. grid (256), 256 thr.
// ===========================================================================
__global__ void __launch_bounds__(256) k_cvtH0(const float* __restrict__ H0) {
    const int m = blockIdx.x;
    for (int k = threadIdx.x * 4; k < HID; k += 1024) {
        float4 v = *reinterpret_cast<const float4*>(H0 + (size_t)m * HID + k);
        size_t d = (size_t)m * HID + k;
        split2(v.x, g_hA_hi[d],     g_hA_lo[d]);
        split2(v.y, g_hA_hi[d + 1], g_hA_lo[d + 1]);
        split2(v.z, g_hA_hi[d + 2], g_hA_lo[d + 2]);
        split2(v.w, g_hA_hi[d + 3], g_hA_lo[d + 3]);
    }
}

// ===========================================================================
// k_h0v2 (unchanged, race-fixed)
// ===========================================================================
#define HBK   16
#define HKPER 2000
#define HNT   125
#define HASZ  (HBK * 36)
#define HBSZ  (HBK * 64)
#define HSTG  (HASZ + HBSZ)
#define HGRP  (3 * HSTG)
#define HSMF  (4 * HGRP)

__global__ void __launch_bounds__(512) k_h0v2(const float* __restrict__ X,
                                              const float* __restrict__ W,
                                              const float* __restrict__ bias,
                                              float* __restrict__ H0) {
    extern __shared__ float sm[];
    const int tid  = threadIdx.x;
    const int g    = tid >> 7;
    const int wtid = tid & 127;
    const int tx   = wtid & 15;
    const int ty   = wtid >> 4;
    const int m0 = blockIdx.y * 32, n0 = blockIdx.x * 64;
    float* gb = sm + g * HGRP;

    float b4x = bias[n0 + (tid & 15) * 4 + 0];
    float b4y = bias[n0 + (tid & 15) * 4 + 1];
    float b4z = bias[n0 + (tid & 15) * 4 + 2];
    float b4w = bias[n0 + (tid & 15) * 4 + 3];

    float2 acc[4][2] = {};

    auto load_tile = [&](int stage, int tl) {
        const int kb = g * HKPER + tl * HBK;
        float* dstA = gb + stage * HSTG;
        const float* asrc = X + (size_t)m0 * KIN + kb;
        #pragma unroll
        for (int i = wtid; i < HBK * 32; i += 128) {
            int k = i & 15, m = i >> 4;
            uint32_t d = (uint32_t)__cvta_generic_to_shared(dstA + k * 36 + m);
            CP4(d, asrc + (size_t)m * KIN + k);
        }
        const float* bsrc = W + (size_t)kb * HID + n0;
        float* dstB = dstA + HASZ;
        #pragma unroll
        for (int i = wtid; i < HBK * 16; i += 128) {
            int k = i >> 4, n4 = i & 15;
            uint32_t d = (uint32_t)__cvta_generic_to_shared(dstB + k * 64 + n4 * 4);
            CP16(d, bsrc + (size_t)k * HID + n4 * 4);
        }
    };

    auto compute = [&](int stage) {
        const float* As_ = gb + stage * HSTG;
        const float* B_  = As_ + HASZ;
        #pragma unroll
        for (int k = 0; k < HBK; k++) {
            float4 a4 = *reinterpret_cast<const float4*>(As_ + k * 36 + ty * 4);
            float2 A0 = make_float2(a4.x, a4.x), A1 = make_float2(a4.y, a4.y);
            float2 A2 = make_float2(a4.z, a4.z), A3 = make_float2(a4.w, a4.w);
            float4 b = *reinterpret_cast<const float4*>(B_ + k * 64 + tx * 4);
            float2 b0 = make_float2(b.x, b.y), b1 = make_float2(b.z, b.w);
            acc[0][0] = ffma2(A0, b0, acc[0][0]); acc[0][1] = ffma2(A0, b1, acc[0][1]);
            acc[1][0] = ffma2(A1, b0, acc[1][0]); acc[1][1] = ffma2(A1, b1, acc[1][1]);
            acc[2][0] = ffma2(A2, b0, acc[2][0]); acc[2][1] = ffma2(A2, b1, acc[2][1]);
            acc[3][0] = ffma2(A3, b0, acc[3][0]); acc[3][1] = ffma2(A3, b1, acc[3][1]);
        }
    };

    load_tile(0, 0); CP_COMMIT();
    load_tile(1, 1); CP_COMMIT();
    int cs = 0, ls = 2;
    for (int tl = 0; tl < HNT; tl++) {
        CP_WAIT(1);
        __syncthreads();
        if (tl + 2 < HNT) load_tile(ls, tl + 2);
        CP_COMMIT();
        compute(cs);
        cs = (cs == 2) ? 0 : cs + 1;
        ls = (ls == 2) ? 0 : ls + 1;
    }
    __syncthreads();

    #pragma unroll
    for (int r = 0; r < 4; r++) {
        float4 v = make_float4(acc[r][0].x, acc[r][0].y, acc[r][1].x, acc[r][1].y);
        *reinterpret_cast<float4*>(gb + (ty * 4 + r) * 64 + tx * 4) = v;
    }
    __syncthreads();

    {
        int row = tid >> 4, c0 = (tid & 15) * 4;
        float s0 = 0.f, s1 = 0.f, s2 = 0.f, s3 = 0.f;
        #pragma unroll
        for (int gg = 0; gg < 4; gg++) {
            float4 p = *reinterpret_cast<const float4*>(sm + gg * HGRP + row * 64 + c0);
            s0 += p.x; s1 += p.y; s2 += p.z; s3 += p.w;
        }
        s0 += b4x; s1 += b4y; s2 += b4z; s3 += b4w;
        float4 o = make_float4(s0 > 0.f ? s0 : 0.f, s1 > 0.f ? s1 : 0.f,
                               s2 > 0.f ? s2 : 0.f, s3 > 0.f ? s3 : 0.f);
        *reinterpret_cast<float4*>(H0 + (size_t)(m0 + row) * HID + n0 + c0) = o;
    }
}

// ===========================================================================
// k_steps_mma v2: persistent HMMA GRU recurrence with fused input GEMM.
// grid (32 slices, 4 m-quarters) = 128 CTAs, 256 threads (8 warps).
// - Wi slice resident in smem; action tile prefetched one step ahead
// - h_prev carried in registers (lane mapping step-invariant)
// - per-mq barrier (32 CTAs each)
// - B chunks 0/1 + action prefetched before the barrier
// ===========================================================================
#define STG_B  23552
#define OFF_AH 0
#define OFF_AL 5120
#define OFF_BH 10240
#define OFF_BL 16896
#define APITCH_B 80             // A row pitch bytes (odd # of 16B) -> conflict-free
#define BPITCH_B 208            // B row pitch bytes (13x16B odd)
#define OFF_WI  (3 * STG_B)                 // 70656: Wi tile [96][36] fp32
#define OFF_AS  (OFF_WI + 96 * 36 * 4)      // 84480: action [2][64][36] fp32
#define SMEM_MMA (OFF_AS + 2 * 64 * 36 * 4) // 102912 B

__global__ void __launch_bounds__(256) k_steps_mma(const float* __restrict__ h0,
                                                   const float* __restrict__ action,
                                                   const float* __restrict__ Wi,
                                                   const float* __restrict__ bi,
                                                   const float* __restrict__ bhn,
                                                   float* __restrict__ outs) {
    extern __shared__ char smem[];
    const uint32_t sb = smem_u32(smem);
    float* wi_s = reinterpret_cast<float*>(smem + OFF_WI);
    float* a_s  = reinterpret_cast<float*>(smem + OFF_AS);

    const int tid = threadIdx.x;
    const int w = tid >> 5, l = tid & 31;
    const int s = blockIdx.x;          // hid slice (32 cols)
    const int mq = blockIdx.y;         // m quarter (64 rows)
    const int wm = w & 3;              // warp m group (16 rows)
    const int wn = w >> 2;             // warp n half (sub 0/1)
    const int lr = l >> 2;             // frag row 0..7
    const int lc2 = (l & 3) * 2;       // frag col pair base

    const int a_row  = wm * 16 + (l & 15);
    const int a_koff = (l >> 4) * 8;
    const int b_krow = (l & 15);
    const int b_noff = wn * 48 + (l >> 4) * 8;

    const int hidbase = s * 32 + wn * 16;

    // bhn lane-local
    float bh[2][2];
    #pragma unroll
    for (int pp = 0; pp < 2; pp++) {
        float2 v = *reinterpret_cast<const float2*>(bhn + hidbase + pp * 8 + lc2);
        bh[pp][0] = v.x; bh[pp][1] = v.y;
    }
    // bi lane-local: [gate][pp][e]
    float biv[3][2][2];
    #pragma unroll
    for (int gate = 0; gate < 3; gate++)
        #pragma unroll
        for (int pp = 0; pp < 2; pp++) {
            float2 v = *reinterpret_cast<const float2*>(bi + gate * HID + hidbase + pp * 8 + lc2);
            biv[gate][pp][0] = v.x; biv[gate][pp][1] = v.y;
        }
    // h_prev lane-local registers, init from h0
    float hpreg[2][2][2];
    #pragma unroll
    for (int rr = 0; rr < 2; rr++) {
        const int m = mq * 64 + wm * 16 + lr + rr * 8;
        #pragma unroll
        for (int pp = 0; pp < 2; pp++) {
            float2 v = *reinterpret_cast<const float2*>(h0 + (size_t)m * HID + hidbase + pp * 8 + lc2);
            hpreg[rr][pp][0] = v.x; hpreg[rr][pp][1] = v.y;
        }
    }

    // Wi slice resident: wi_s[col 96][36] ; col = gate*32 + cl, hid = s*32 + cl
    for (int i = tid; i < 96 * 32; i += 256) {
        int col = i >> 5, k = i & 31;
        int gate = col >> 5, cl = col & 31;
        wi_s[col * 36 + k] = Wi[(size_t)k * G3 + gate * HID + s * 32 + cl];
    }
    __syncthreads();

    const char* srcBH = (const char*)(g_wBp_hi + (size_t)s * HID * 96);
    const char* srcBL = (const char*)(g_wBp_lo + (size_t)s * HID * 96);

    auto load_B = [&](int ch, int st) {
        uint32_t base = sb + st * STG_B;
        #pragma unroll
        for (int i = tid; i < 384; i += 256) {
            int r = i / 12, sg = i % 12;
            const char* sp = srcBH + ((size_t)(ch * 32 + r)) * 192 + sg * 16;
            CP16(base + OFF_BH + r * BPITCH_B + sg * 16, sp);
            const char* sp2 = srcBL + ((size_t)(ch * 32 + r)) * 192 + sg * 16;
            CP16(base + OFF_BL + r * BPITCH_B + sg * 16, sp2);
        }
    };
    auto load_act = [&](int tt) {
        uint32_t ab = sb + OFF_AS + (tt & 1) * (64 * 36 * 4);
        #pragma unroll
        for (int i = tid; i < 512; i += 256) {
            int row = i >> 3, seg = i & 7;
            const float* src = action + ((size_t)(mq * 64 + row) * NT + tt) * ACT + seg * 4;
            CP16(ab + row * 144 + seg * 16, src);
        }
    };

    // step-0 prefetch: B chunks 0,1 + action(0)
    load_B(0, 0); load_act(0); CP_COMMIT();   // G1
    load_B(1, 1); CP_COMMIT();                // G2

    #pragma unroll 1
    for (int t = 0; t < NT; t++) {
        const int rbuf = t & 1;
        const char* srcAH = (const char*)(g_hA_hi + (size_t)rbuf * BS * HID + (size_t)mq * 64 * HID);
        const char* srcAL = (const char*)(g_hA_lo + (size_t)rbuf * BS * HID + (size_t)mq * 64 * HID);

        auto load_A = [&](int ch, int st) {
            uint32_t base = sb + st * STG_B;
            int row = tid >> 2, seg = tid & 3;
            const char* sa = srcAH + (size_t)row * (HID * 2) + ch * 64 + seg * 16;
            CP16(base + OFF_AH + row * APITCH_B + seg * 16, sa);
            const char* sa2 = srcAL + (size_t)row * (HID * 2) + ch * 64 + seg * 16;
            CP16(base + OFF_AL + row * APITCH_B + seg * 16, sa2);
        };

        // ---- per-mq barrier: release means all h_{t-1} A-image writes visible ----
        if (t > 0) {
            if (tid == 0) {
                unsigned* ctr = &g_bars[mq * 32];
                const unsigned target = 32u * (unsigned)t;
                atomicAdd(ctr, 1u);
                unsigned v;
                do {
                    asm volatile("ld.volatile.global.u32 %0, [%1];" : "=r"(v) : "l"(ctr));
                } while (v < target);
            }
            __syncthreads();
            __threadfence();
        }

        load_A(0, 0); CP_COMMIT();   // G3
        load_A(1, 1); CP_COMMIT();   // G4

        float c[6][4] = {};

        auto compute = [&](int st) {
            uint32_t base = sb + st * STG_B;
            #pragma unroll
            for (int kk = 0; kk < 2; kk++) {
                const int k0 = kk * 16;
                uint32_t aH[4], aL[4];
                uint32_t adA = base + OFF_AH + a_row * APITCH_B + (k0 + a_koff) * 2;
                LDSM4(aH, adA);
                LDSM4(aL, adA + (OFF_AL - OFF_AH));
                uint32_t bH[6][2], bL[6][2];
                #pragma unroll
                for (int g2 = 0; g2 < 3; g2++) {
                    uint32_t adB = base + OFF_BH + (k0 + b_krow) * BPITCH_B + (b_noff + g2 * 16) * 2;
                    uint32_t r4[4];
                    LDSM4T(r4, adB);
                    bH[g2 * 2][0] = r4[0]; bH[g2 * 2][1] = r4[1];
                    bH[g2 * 2 + 1][0] = r4[2]; bH[g2 * 2 + 1][1] = r4[3];
                    LDSM4T(r4, adB + (OFF_BL - OFF_BH));
                    bL[g2 * 2][0] = r4[0]; bL[g2 * 2][1] = r4[1];
                    bL[g2 * 2 + 1][0] = r4[2]; bL[g2 * 2 + 1][1] = r4[3];
                }
                #pragma unroll
                for (int g = 0; g < 6; g++) {
                    mma16816(c[g], aH, bH[g]);
                    mma16816(c[g], aH, bL[g]);
                    mma16816(c[g], aL, bH[g]);
                }
            }
        };

        #pragma unroll 1
        for (int ch = 0; ch < 32; ch++) {
            CP_WAIT(1);
            __syncthreads();
            if (ch + 2 < 32) {
                int st2 = (ch + 2) % 3;
                load_A(ch + 2, st2);
                load_B(ch + 2, st2);
            }
            CP_COMMIT();
            compute(ch % 3);
        }
        __syncthreads();   // all computes done before stage smem reused

        // prefetch next step's B chunks + action (input data; pre-barrier OK)
        if (t + 1 < NT) {
            load_B(0, 0); load_act(t + 1); CP_COMMIT();
            load_B(1, 1); CP_COMMIT();
        }

        // ---- fused input GEMM: giv = a_t @ Wi + bi (lane-local) ----
        float giv[2][12];
        #pragma unroll
        for (int rr = 0; rr < 2; rr++)
            #pragma unroll
            for (int gate = 0; gate < 3; gate++)
                #pragma unroll
                for (int pp = 0; pp < 2; pp++) {
                    giv[rr][gate * 4 + pp * 2 + 0] = biv[gate][pp][0];
                    giv[rr][gate * 4 + pp * 2 + 1] = biv[gate][pp][1];
                }
        {
            const float* ab = a_s + (t & 1) * (64 * 36);
            const float* r0 = ab + (wm * 16 + lr) * 36;
            const float* r1 = r0 + 8 * 36;
            #pragma unroll
            for (int k4 = 0; k4 < 8; k4++) {
                float4 a0 = *reinterpret_cast<const float4*>(r0 + k4 * 4);
                float4 a1 = *reinterpret_cast<const float4*>(r1 + k4 * 4);
                #pragma unroll
                for (int gate = 0; gate < 3; gate++)
                    #pragma unroll
                    for (int pp = 0; pp < 2; pp++)
                        #pragma unroll
                        for (int e = 0; e < 2; e++) {
                            int col = gate * 32 + wn * 16 + pp * 8 + lc2 + e;
                            float4 wv = *reinterpret_cast<const float4*>(wi_s + col * 36 + k4 * 4);
                            int j = gate * 4 + pp * 2 + e;
                            giv[0][j] += a0.x * wv.x + a0.y * wv.y + a0.z * wv.z + a0.w * wv.w;
                            giv[1][j] += a1.x * wv.x + a1.y * wv.y + a1.z * wv.z + a1.w * wv.w;
                        }
            }
        }

        // ---- epilogue: lane-local GRU pointwise, h_prev in regs ----
        #pragma unroll
        for (int rr = 0; rr < 2; rr++) {
            const int m = mq * 64 + wm * 16 + lr + rr * 8;
            float* orow = outs + ((size_t)t * BS + m) * HID;
            #pragma unroll
            for (int pp = 0; pp < 2; pp++) {
                const int hid = hidbase + pp * 8 + lc2;
                float h[2];
                #pragma unroll
                for (int e = 0; e < 2; e++) {
                    float rv = c[pp][2 * rr + e];
                    float zv = c[2 + pp][2 * rr + e];
                    float nv = c[4 + pp][2 * rr + e];
                    float rg = fast_sigmoid(rv + giv[rr][0 * 4 + pp * 2 + e]);
                    float zg = fast_sigmoid(zv + giv[rr][1 * 4 + pp * 2 + e]);
                    float ng = fast_tanh(giv[rr][2 * 4 + pp * 2 + e] + rg * (nv + bh[pp][e]));
                    h[e] = (1.0f - zg) * ng + zg * hpreg[rr][pp][e];
                    hpreg[rr][pp][e] = h[e];
                }
                *reinterpret_cast<float2*>(orow + hid) = make_float2(h[0], h[1]);
                if (t + 1 < NT) {
                    const int wbuf = (t + 1) & 1;
                    size_t d = (size_t)wbuf * BS * HID + (size_t)m * HID + hid;
                    unsigned short hi0, hi1, lo0, lo1;
                    split2(h[0], hi0, lo0);
                    split2(h[1], hi1, lo1);
                    *reinterpret_cast<uint32_t*>(g_hA_hi + d) = ((uint32_t)hi1 << 16) | hi0;
                    *reinterpret_cast<uint32_t*>(g_hA_lo + d) = ((uint32_t)lo1 << 16) | lo0;
                }
            }
        }

        // publish A-image writes before arriving at next step's barrier
        if (t + 1 < NT) {
            __threadfence();
            __syncthreads();
        }
    }
}

// ===========================================================================
// k_out (unchanged)
// ===========================================================================
__global__ void __launch_bounds__(256) k_out(const float* __restrict__ outs,
                                             const float* __restrict__ Wo,
                                             const float* __restrict__ bo,
                                             float* __restrict__ out) {
    __shared__ float As[32][33];
    __shared__ float Bs[32][64];
    const int tx = threadIdx.x, ty = threadIdx.y;
    const int tid = ty * 16 + tx;
    const int R0 = blockIdx.x * 32;
    float2 acc[2][2] = {};

    for (int k0 = 0; k0 < HID; k0 += 32) {
        #pragma unroll
        for (int i = tid; i < 32 * 32; i += 256) {
            int m = i >> 5, k = i & 31;
            As[k][m] = outs[(size_t)(R0 + m) * HID + k0 + k];
        }
        #pragma unroll
        for (int i = tid; i < 32 * 64; i += 256) {
            int k = i >> 6, n = i & 63;
            Bs[k][n] = Wo[(size_t)(k0 + k) * OUTD + n];
        }
        __syncthreads();
        #pragma unroll
        for (int k = 0; k < 32; k++) {
            float a0 = As[k][ty * 2 + 0], a1 = As[k][ty * 2 + 1];
            float2 A0 = make_float2(a0, a0), A1 = make_float2(a1, a1);
            const float2* bp = reinterpret_cast<const float2*>(&Bs[k][tx * 4]);
            float2 b0 = bp[0], b1 = bp[1];
            acc[0][0] = ffma2(A0, b0, acc[0][0]);
            acc[0][1] = ffma2(A0, b1, acc[0][1]);
            acc[1][0] = ffma2(A1, b0, acc[1][0]);
            acc[1][1] = ffma2(A1, b1, acc[1][1]);
        }
        __syncthreads();
    }

    #pragma unroll
    for (int r = 0; r < 2; r++) {
        int R = R0 + ty * 2 + r;
        int tt = R >> 8;
        int b  = R & (BS - 1);
        #pragma unroll
        for (int c = 0; c < 2; c++) {
            int n = tx * 4 + c * 2;
            out[((size_t)b * NT + tt) * OUTD + n]     = acc[r][c].x + bo[n];
            out[((size_t)b * NT + tt) * OUTD + n + 1] = acc[r][c].y + bo[n + 1];
        }
    }
}

extern "C" void kernel_launch(void* const* d_in, const int* in_sizes, int n_in,
                              void* d_out, int out_size) {
    const float* history = (const float*)d_in[0];
    const float* action  = (const float*)d_in[1];
    const float* W_in    = (const float*)d_in[2];
    const float* b_in    = (const float*)d_in[3];
    const float* Wi      = (const float*)d_in[4];
    const float* bi      = (const float*)d_in[5];
    const float* Wh      = (const float*)d_in[6];
    const float* bhn     = (const float*)d_in[7];
    const float* Wo      = (const float*)d_in[8];
    const float* bo      = (const float*)d_in[9];
    float* out = (float*)d_out;

    float *h0buf = nullptr, *outsbuf = nullptr;
    cudaGetSymbolAddress((void**)&h0buf, g_h0);
    cudaGetSymbolAddress((void**)&outsbuf, g_outs);

    const int smem_h0 = HSMF * 4;
    cudaFuncSetAttribute(k_h0v2, cudaFuncAttributeMaxDynamicSharedMemorySize, smem_h0);
    cudaFuncSetAttribute(k_steps_mma, cudaFuncAttributeMaxDynamicSharedMemorySize, SMEM_MMA);

    k_zero<<<1, 128>>>();
    k_h0v2<<<dim3(HID / 64, BS / 32), 512, smem_h0>>>(history, W_in, b_in, h0buf);
    k_packW<<<dim3(32, 16), 256>>>(Wh);
    k_cvtH0<<<BS, 256>>>(h0buf);

    k_steps_mma<<<dim3(32, 4), 256, SMEM_MMA>>>(h0buf, action, Wi, bi, bhn, outsbuf);

    k_out<<<dim3(NT * BS / 32), dim3(16, 16)>>>(outsbuf, Wo, bo, out);
}